// round 11
// baseline (speedup 1.0000x reference)
#include <cuda_runtime.h>
#include <cstdint>
#include <math.h>

// ---------------- problem constants ----------------
#define SEQ     2048
#define DMODEL  2048
#define KVDIM   512
#define NHEADS  16
#define DK      128
#define NQKV    (DMODEL + 2 * KVDIM)    // 3072

// ---------------- scratch ----------------
__device__ float g_QKV [SEQ * NQKV];
__device__ float g_Y   [SEQ * DMODEL];
__device__ float g_xt  [SEQ * DMODEL];
__device__ float g_Wqkv[NQKV * DMODEL];
__device__ float g_bqkv[NQKV];
__device__ float g_Wot [DMODEL * DMODEL];

// =====================================================================
// helpers
// =====================================================================
__device__ __forceinline__ float rnaf(float x) {
    uint32_t u;
    asm("cvt.rna.tf32.f32 %0, %1;" : "=r"(u) : "f"(x));
    return __uint_as_float(u);
}

__device__ __forceinline__ void cpasync16(uint32_t saddr, const void* gaddr) {
    asm volatile("cp.async.cg.shared.global [%0], [%1], 16;" :: "r"(saddr), "l"(gaddr) : "memory");
}

__device__ __forceinline__ void mma_tf32(float c[4], const uint32_t a[4], const uint32_t b[2]) {
    asm volatile(
        "mma.sync.aligned.m16n8k8.row.col.f32.tf32.tf32.f32 "
        "{%0,%1,%2,%3}, {%4,%5,%6,%7}, {%8,%9}, {%0,%1,%2,%3};"
        : "+f"(c[0]), "+f"(c[1]), "+f"(c[2]), "+f"(c[3])
        : "r"(a[0]), "r"(a[1]), "r"(a[2]), "r"(a[3]), "r"(b[0]), "r"(b[1]));
}

__device__ __forceinline__ void ldsm_x4(uint32_t r[4], uint32_t addr) {
    asm volatile("ldmatrix.sync.aligned.m8n8.x4.shared.b16 {%0,%1,%2,%3}, [%4];"
                 : "=r"(r[0]), "=r"(r[1]), "=r"(r[2]), "=r"(r[3]) : "r"(addr));
}

// =====================================================================
// fused tf32-rounding + bias-fusion pass
// =====================================================================
#define N4_BIG (SEQ * DMODEL / 4)
#define N4_KV  (KVDIM * DMODEL / 4)
#define CVT_TOTAL (3 * N4_BIG + 2 * N4_KV)

__global__ void cvt_all_kernel(
    const float4* __restrict__ x,  const float4* __restrict__ wq,
    const float4* __restrict__ wk, const float4* __restrict__ wv,
    const float4* __restrict__ wo,
    const float*  __restrict__ bq, const float* __restrict__ bk,
    const float*  __restrict__ bv,
    float4* __restrict__ xt, float4* __restrict__ wqkv,
    float4* __restrict__ wot, float* __restrict__ bqkv)
{
    int i = blockIdx.x * blockDim.x + threadIdx.x;
    if (i < CVT_TOTAL) {
        const float4* src;
        float4* dst;
        int j = i;
        if (j < N4_BIG)                    { src = x;  dst = xt; }
        else if ((j -= N4_BIG) < N4_BIG)   { src = wq; dst = wqkv; }
        else if ((j -= N4_BIG) < N4_KV)    { src = wk; dst = wqkv + N4_BIG; }
        else if ((j -= N4_KV)  < N4_KV)    { src = wv; dst = wqkv + N4_BIG + N4_KV; }
        else { j -= N4_KV;                   src = wo; dst = wot; }
        float4 v = src[j];
        float4 o;
        o.x = rnaf(v.x); o.y = rnaf(v.y); o.z = rnaf(v.z); o.w = rnaf(v.w);
        dst[j] = o;
    } else {
        int j = i - CVT_TOTAL;
        if (j < NQKV) {
            float v;
            if (j < DMODEL)              v = bq[j];
            else if (j < DMODEL + KVDIM) v = bk[j - DMODEL];
            else                         v = bv[j - DMODEL - KVDIM];
            bqkv[j] = v;
        }
    }
}

// =====================================================================
// tf32 mma.sync GEMM — CTA 128x128, 8 warps (2x4), warp tile 64x32,
// BK=32, 3-stage cp.async, 2 CTAs/SM, explicit fragment double-buffer.
// =====================================================================
#define BK      32
#define PAD     36
#define TILE_F  (128 * PAD)
#define STAGE_F (2 * TILE_F)
#define NSTAGE  3
#define GEMM_SMEM_BYTES (NSTAGE * STAGE_F * 4)

template <bool ROUND>
__global__ __launch_bounds__(256, 2) void gemm_tf32(
    const float* __restrict__ A, const float* __restrict__ B,
    const float* __restrict__ bias, float* __restrict__ C,
    int M, int N, int K)
{
    extern __shared__ float sm[];

    const int tid  = threadIdx.x;
    const int wid  = tid >> 5;
    const int lane = tid & 31;
    const int gid  = lane >> 2;
    const int tig  = lane & 3;
    const int wm   = wid >> 2;
    const int wn   = wid & 3;
    const int bm   = blockIdx.y * 128;
    const int bn   = blockIdx.x * 128;
    const int nchunk = K >> 5;

    const int arow = lane & 15;
    const int acsh = (lane >> 4) * 4;
    const int brow = ((lane >> 4) << 3) + (lane & 7);
    const int bcsh = ((lane >> 3) & 1) * 4;

    const uint32_t smem_u32 = (uint32_t)__cvta_generic_to_shared(sm);

    auto load_chunk = [&](int s, int j) {
        const uint32_t sA = smem_u32 + (s * STAGE_F) * 4;
        const uint32_t sB = sA + TILE_F * 4;
        const float* Ag = A + (size_t)bm * K + j * BK;
        const float* Bg = B + (size_t)bn * K + j * BK;
#pragma unroll
        for (int it = 0; it < 4; it++) {
            const int idx = tid + it * 256;
            const int r = idx >> 3;
            const int c = idx & 7;
            const uint32_t soff = (r * PAD + c * 4) * 4;
            cpasync16(sA + soff, Ag + (size_t)r * K + c * 4);
            cpasync16(sB + soff, Bg + (size_t)r * K + c * 4);
        }
        asm volatile("cp.async.commit_group;" ::: "memory");
    };

    float acc[4][4][4];
#pragma unroll
    for (int mf = 0; mf < 4; mf++)
#pragma unroll
        for (int nf = 0; nf < 4; nf++)
#pragma unroll
            for (int q = 0; q < 4; q++) acc[mf][nf][q] = 0.0f;

    load_chunk(0, 0);
    if (nchunk > 1) load_chunk(1, 1);

    int cs = 0;
    int ls = 2;
    for (int i = 0; i < nchunk; i++) {
        if (i + 1 < nchunk) {
            asm volatile("cp.async.wait_group 1;" ::: "memory");
        } else {
            asm volatile("cp.async.wait_group 0;" ::: "memory");
        }
        __syncthreads();

        const uint32_t stA = smem_u32 + (cs * STAGE_F) * 4;
        const uint32_t stB = stA + TILE_F * 4;
        const uint32_t aAddr = stA + ((wm * 64 + arow) * PAD + acsh) * 4;
        const uint32_t bAddr = stB + ((wn * 32 + brow) * PAD + bcsh) * 4;
        cs = (cs == NSTAGE - 1) ? 0 : cs + 1;

        // ---- preload slice 0 fragments (critical path first) ----
        uint32_t af[2][4][4];
        uint32_t bf[2][4][2];
#pragma unroll
        for (int mf = 0; mf < 4; mf++)
            ldsm_x4(af[0][mf], aAddr + (mf * 16 * PAD) * 4);
#pragma unroll
        for (int np = 0; np < 2; np++) {
            uint32_t bt[4];
            ldsm_x4(bt, bAddr + (np * 16 * PAD) * 4);
            bf[0][2 * np][0]     = bt[0]; bf[0][2 * np][1]     = bt[1];
            bf[0][2 * np + 1][0] = bt[2]; bf[0][2 * np + 1][1] = bt[3];
        }

        // issue next chunk's cp.async after the first fragment burst
        const int j = i + 2;
        if (j < nchunk) {
            load_chunk(ls, j);
            ls = (ls == NSTAGE - 1) ? 0 : ls + 1;
        }

        // ---- kk loop: ldsm slice kk+1 overlaps MMAs of slice kk ----
#pragma unroll
        for (int kk = 0; kk < 4; kk++) {
            const int cur = kk & 1;
            const int nxt = cur ^ 1;
            if (kk < 3) {
                const int k0 = (kk + 1) * 8;
#pragma unroll
                for (int mf = 0; mf < 4; mf++)
                    ldsm_x4(af[nxt][mf], aAddr + (mf * 16 * PAD + k0) * 4);
#pragma unroll
                for (int np = 0; np < 2; np++) {
                    uint32_t bt[4];
                    ldsm_x4(bt, bAddr + (np * 16 * PAD + k0) * 4);
                    bf[nxt][2 * np][0]     = bt[0]; bf[nxt][2 * np][1]     = bt[1];
                    bf[nxt][2 * np + 1][0] = bt[2]; bf[nxt][2 * np + 1][1] = bt[3];
                }
            }
#pragma unroll
            for (int mf = 0; mf < 4; mf++)
#pragma unroll
                for (int nf = 0; nf < 4; nf++)
                    mma_tf32(acc[mf][nf], af[cur][mf], bf[cur][nf]);
        }
    }

#pragma unroll
    for (int mf = 0; mf < 4; mf++) {
        const int row = bm + wm * 64 + mf * 16 + gid;
#pragma unroll
        for (int nf = 0; nf < 4; nf++) {
            const int col = bn + wn * 32 + nf * 8 + 2 * tig;
            const float b0 = bias[col], b1 = bias[col + 1];
            float2 v0, v1;
            if (ROUND) {
                v0.x = rnaf(acc[mf][nf][0] + b0); v0.y = rnaf(acc[mf][nf][1] + b1);
                v1.x = rnaf(acc[mf][nf][2] + b0); v1.y = rnaf(acc[mf][nf][3] + b1);
            } else {
                v0.x = acc[mf][nf][0] + b0; v0.y = acc[mf][nf][1] + b1;
                v1.x = acc[mf][nf][2] + b0; v1.y = acc[mf][nf][3] + b1;
            }
            *(float2*)&C[(size_t)row * N + col]       = v0;
            *(float2*)&C[(size_t)(row + 8) * N + col] = v1;
        }
    }
}

// =====================================================================
// Flash attention v4: paired q-blocks for causal load balance.
// =====================================================================
#define QT    128
#define KT    64
#define DPAD  132
#define VPAD  68
#define PPAD  68
#define KOFF  0
#define VOFF  (2 * KT * DPAD)
#define POFF  (VOFF + 2 * QT * VPAD)
#define ATTN_F (POFF + QT * PPAD)
#define ATTN_SMEM_BYTES (ATTN_F * 4)
#define NQB   (SEQ / QT)                 // 16

__global__ __launch_bounds__(256, 1) void attn_tc_kernel(
    const float* __restrict__ QKV, float* __restrict__ Y)
{
    extern __shared__ float sm[];

    const int h    = blockIdx.y;
    const int pair = blockIdx.x;            // 0..7
    const int kvh  = h >> 2;
    const int tid  = threadIdx.x;
    const int wid  = tid >> 5;
    const int lane = tid & 31;
    const int gid  = lane >> 2;
    const int tig  = lane & 3;
    const int w16  = wid * 16;

    const int arow = lane & 15;
    const int acsh = (lane >> 4) * 4;
    const int brow = ((lane >> 4) << 3) + (lane & 7);
    const int bcsh = ((lane >> 3) & 1) * 4;

    const uint32_t smem_u32 = (uint32_t)__cvta_generic_to_shared(sm);

    const float* Qg = QKV + h * DK;
    const float* Kg = QKV + DMODEL + kvh * DK;
    const float* Vg = QKV + DMODEL + KVDIM + kvh * DK;

    const uint32_t kBase = smem_u32 + (KOFF + brow * DPAD + bcsh) * 4;
    const uint32_t vBase = smem_u32 + (VOFF + brow * VPAD + bcsh) * 4;
    const uint32_t pAddr = smem_u32 + (POFF + (w16 + arow) * PPAD + acsh) * 4;
    float* Ps = sm + POFF;

    const int vbr0 = tid >> 5;
    const int vbc0 = tid & 31;
    const float scale = 0.08838834764831845f;

    auto issue_K = [&](int jbi, int buf) {
        const float* src = Kg + (size_t)(jbi * KT) * NQKV;
        const uint32_t dst = smem_u32 + (KOFF + buf * KT * DPAD) * 4;
#pragma unroll
        for (int it = 0; it < 8; it++) {
            const int idx = tid + it * 256;
            const int r = idx >> 5;
            const int c = idx & 31;
            cpasync16(dst + (r * DPAD + c * 4) * 4, src + (size_t)r * NQKV + c * 4);
        }
        asm volatile("cp.async.commit_group;" ::: "memory");
    };
    auto ldg_V = [&](int jbi, float4 vb[2][4]) {
        const float* src = Vg + (size_t)(jbi * KT) * NQKV;
#pragma unroll
        for (int b = 0; b < 2; b++) {
            const int br = vbr0 + b * 8;
#pragma unroll
            for (int j = 0; j < 4; j++)
                vb[b][j] = *(const float4*)&src[(size_t)(br * 4 + j) * NQKV + vbc0 * 4];
        }
    };
    auto sts_Vt = [&](int buf, float4 vb[2][4]) {
        float* Vt = sm + VOFF + buf * QT * VPAD;
#pragma unroll
        for (int b = 0; b < 2; b++) {
            const int br = vbr0 + b * 8;
            const float* v = (const float*)vb[b];
#pragma unroll
            for (int k = 0; k < 4; k++) {
                float4 w;
                w.x = v[0 * 4 + k]; w.y = v[1 * 4 + k];
                w.z = v[2 * 4 + k]; w.w = v[3 * 4 + k];
                *(float4*)&Vt[(vbc0 * 4 + k) * VPAD + br * 4] = w;
            }
        }
    };

    for (int half = 0; half < 2; half++) {
        const int qb = half ? pair : (NQB - 1 - pair);
        const int q0 = qb * QT;
        const int rg0 = q0 + w16 + gid;
        const int rg1 = rg0 + 8;
        const int njb = 2 * qb + 2;

        asm volatile("cp.async.wait_group 0;" ::: "memory");
        __syncthreads();

        // ---- stage Q (pre-rounded tf32) into K region, ldsm to regs ----
        for (int i = tid; i < QT * 32; i += 256) {
            const int r  = i >> 5;
            const int c4 = (i & 31) << 2;
            *(float4*)&sm[r * DPAD + c4] = *(const float4*)&Qg[(size_t)(q0 + r) * NQKV + c4];
        }
        __syncthreads();
        uint32_t qf[16][4];
        {
            const uint32_t qAddr = smem_u32 + ((w16 + arow) * DPAD + acsh) * 4;
#pragma unroll
            for (int kk = 0; kk < 16; kk++)
                ldsm_x4(qf[kk], qAddr + kk * 32);
        }
        __syncthreads();

        float o_acc[16][4];
#pragma unroll
        for (int nf = 0; nf < 16; nf++)
#pragma unroll
            for (int q = 0; q < 4; q++) o_acc[nf][q] = 0.0f;
        float m0 = -1e30f, m1 = -1e30f, l0 = 0.0f, l1 = 0.0f;

        issue_K(0, 0);
        {
            float4 vb[2][4];
            ldg_V(0, vb);
            sts_Vt(0, vb);
        }

        for (int jb = 0; jb < njb; jb++) {
            const int buf = jb & 1;

            asm volatile("cp.async.wait_group 0;" ::: "memory");
            __syncthreads();

            const bool have_next = (jb + 1 < njb);
            float4 vb[2][4];
            if (have_next) {
                issue_K(jb + 1, buf ^ 1);
                ldg_V(jb + 1, vb);
            }

            // ---- S = Q @ K^T ----
            float s[8][4];
#pragma unroll
            for (int nf = 0; nf < 8; nf++)
#pragma unroll
                for (int q = 0; q < 4; q++) s[nf][q] = 0.0f;

            const uint32_t kAddr = kBase + (buf * KT * DPAD) * 4;
#pragma unroll
            for (int kk = 0; kk < 16; kk++) {
                const int kd = kk * 8;
                uint32_t bf[8][2];
#pragma unroll
                for (int np = 0; np < 4; np++) {
                    uint32_t bt[4];
                    ldsm_x4(bt, kAddr + (np * 16 * DPAD + kd) * 4);
                    bf[2 * np][0]     = bt[0]; bf[2 * np][1]     = bt[1];
                    bf[2 * np + 1][0] = bt[2]; bf[2 * np + 1][1] = bt[3];
                }
#pragma unroll
                for (int nf = 0; nf < 8; nf++)
                    mma_tf32(s[nf], qf[kk], bf[nf]);
            }

            // ---- scale + mask + online softmax ----
            const int k0 = jb * KT;
            const bool need_mask = (jb >= 2 * qb);
            float mx0 = -1e30f, mx1 = -1e30f;
#pragma unroll
            for (int nf = 0; nf < 8; nf++) {
#pragma unroll
                for (int e = 0; e < 2; e++) {
                    const int jg = k0 + nf * 8 + 2 * tig + e;
                    float v0 = s[nf][e]     * scale;
                    float v1 = s[nf][2 + e] * scale;
                    if (need_mask) {
                        if (jg > rg0) v0 = -1e30f;
                        if (jg > rg1) v1 = -1e30f;
                    }
                    s[nf][e]     = v0;
                    s[nf][2 + e] = v1;
                    mx0 = fmaxf(mx0, v0);
                    mx1 = fmaxf(mx1, v1);
                }
            }
            mx0 = fmaxf(mx0, __shfl_xor_sync(0xffffffffu, mx0, 1));
            mx0 = fmaxf(mx0, __shfl_xor_sync(0xffffffffu, mx0, 2));
            mx1 = fmaxf(mx1, __shfl_xor_sync(0xffffffffu, mx1, 1));
            mx1 = fmaxf(mx1, __shfl_xor_sync(0xffffffffu, mx1, 2));

            const float mn0 = fmaxf(m0, mx0);
            const float mn1 = fmaxf(m1, mx1);
            const float al0 = __expf(m0 - mn0);
            const float al1 = __expf(m1 - mn1);
            m0 = mn0; m1 = mn1;

            float sum0 = 0.0f, sum1 = 0.0f;
#pragma unroll
            for (int nf = 0; nf < 8; nf++) {
                float p00 = __expf(s[nf][0] - mn0);
                float p01 = __expf(s[nf][1] - mn0);
                float p10 = __expf(s[nf][2] - mn1);
                float p11 = __expf(s[nf][3] - mn1);
                sum0 += p00 + p01;
                sum1 += p10 + p11;
                float2 w0; w0.x = rnaf(p00); w0.y = rnaf(p01);
                float2 w1; w1.x = rnaf(p10); w1.y = rnaf(p11);
                const int pc = nf * 8 + 2 * tig;
                *(float2*)&Ps[(w16 + gid)     * PPAD + pc] = w0;
                *(float2*)&Ps[(w16 + gid + 8) * PPAD + pc] = w1;
            }
            sum0 += __shfl_xor_sync(0xffffffffu, sum0, 1);
            sum0 += __shfl_xor_sync(0xffffffffu, sum0, 2);
            sum1 += __shfl_xor_sync(0xffffffffu, sum1, 1);
            sum1 += __shfl_xor_sync(0xffffffffu, sum1, 2);
            l0 = l0 * al0 + sum0;
            l1 = l1 * al1 + sum1;

#pragma unroll
            for (int nf = 0; nf < 16; nf++) {
                o_acc[nf][0] *= al0; o_acc[nf][1] *= al0;
                o_acc[nf][2] *= al1; o_acc[nf][3] *= al1;
            }

            if (have_next) sts_Vt(buf ^ 1, vb);
            __syncwarp();

            // ---- O += P @ V ----
            const uint32_t vAddr = vBase + (buf * QT * VPAD) * 4;
#pragma unroll
            for (int kk = 0; kk < 8; kk++) {
                const int kb = kk * 8;
                uint32_t a[4];
                ldsm_x4(a, pAddr + kb * 4);
                uint32_t bf[16][2];
#pragma unroll
                for (int np = 0; np < 8; np++) {
                    uint32_t bt[4];
                    ldsm_x4(bt, vAddr + (np * 16 * VPAD + kb) * 4);
                    bf[2 * np][0]     = bt[0]; bf[2 * np][1]     = bt[1];
                    bf[2 * np + 1][0] = bt[2]; bf[2 * np + 1][1] = bt[3];
                }
#pragma unroll
                for (int nf = 0; nf < 16; nf++)
                    mma_tf32(o_acc[nf], a, bf[nf]);
            }
        }

        // ---- epilogue for this half ----
        const float inv0 = 1.0f / l0;
        const float inv1 = 1.0f / l1;
#pragma unroll
        for (int nf = 0; nf < 16; nf++) {
            const int col = h * DK + nf * 8 + 2 * tig;
            float2 v0, v1;
            v0.x = rnaf(o_acc[nf][0] * inv0); v0.y = rnaf(o_acc[nf][1] * inv0);
            v1.x = rnaf(o_acc[nf][2] * inv1); v1.y = rnaf(o_acc[nf][3] * inv1);
            *(float2*)&Y[(size_t)rg0 * DMODEL + col] = v0;
            *(float2*)&Y[(size_t)rg1 * DMODEL + col] = v1;
        }
    }
}

// =====================================================================
// launch
// =====================================================================
extern "C" void kernel_launch(void* const* d_in, const int* in_sizes, int n_in,
                              void* d_out, int out_size)
{
    const float* x  = (const float*)d_in[0];
    const float* Wq = (const float*)d_in[1];
    const float* bq = (const float*)d_in[2];
    const float* Wk = (const float*)d_in[3];
    const float* bk = (const float*)d_in[4];
    const float* Wv = (const float*)d_in[5];
    const float* bv = (const float*)d_in[6];
    const float* Wo = (const float*)d_in[7];
    const float* bo = (const float*)d_in[8];
    float* out = (float*)d_out;

    float *QKVb, *Yb, *xt, *Wqkv, *bqkv, *Wot;
    cudaGetSymbolAddress((void**)&QKVb, g_QKV);
    cudaGetSymbolAddress((void**)&Yb,   g_Y);
    cudaGetSymbolAddress((void**)&xt,   g_xt);
    cudaGetSymbolAddress((void**)&Wqkv, g_Wqkv);
    cudaGetSymbolAddress((void**)&bqkv, g_bqkv);
    cudaGetSymbolAddress((void**)&Wot,  g_Wot);

    cudaFuncSetAttribute(gemm_tf32<true>,
                         cudaFuncAttributeMaxDynamicSharedMemorySize, GEMM_SMEM_BYTES);
    cudaFuncSetAttribute(gemm_tf32<false>,
                         cudaFuncAttributeMaxDynamicSharedMemorySize, GEMM_SMEM_BYTES);
    cudaFuncSetAttribute(attn_tc_kernel,
                         cudaFuncAttributeMaxDynamicSharedMemorySize, ATTN_SMEM_BYTES);

    dim3 blk(256);

    const int cvt_n = CVT_TOTAL + NQKV;
    cvt_all_kernel<<<(cvt_n + 255) / 256, 256>>>(
        (const float4*)x, (const float4*)Wq, (const float4*)Wk,
        (const float4*)Wv, (const float4*)Wo,
        bq, bk, bv,
        (float4*)xt, (float4*)Wqkv, (float4*)Wot, bqkv);

    gemm_tf32<true><<<dim3(NQKV / 128, SEQ / 128), blk, GEMM_SMEM_BYTES>>>(
        xt, Wqkv, bqkv, QKVb, SEQ, NQKV, DMODEL);

    attn_tc_kernel<<<dim3(NQB / 2, NHEADS), blk, ATTN_SMEM_BYTES>>>(QKVb, Yb);

    gemm_tf32<false><<<dim3(DMODEL / 128, SEQ / 128), blk, GEMM_SMEM_BYTES>>>(
        Yb, Wot, bo, out, SEQ, DMODEL, DMODEL);
}

// round 12
// speedup vs baseline: 1.0293x; 1.0293x over previous
#include <cuda_runtime.h>
#include <cstdint>
#include <math.h>

// ---------------- problem constants ----------------
#define SEQ     2048
#define DMODEL  2048
#define KVDIM   512
#define NHEADS  16
#define DK      128
#define NQKV    (DMODEL + 2 * KVDIM)    // 3072

// ---------------- scratch ----------------
__device__ float g_QKV [SEQ * NQKV];
__device__ float g_Y   [SEQ * DMODEL];
__device__ float g_xt  [SEQ * DMODEL];
__device__ float g_Wqkv[NQKV * DMODEL];
__device__ float g_bqkv[NQKV];
__device__ float g_Wot [DMODEL * DMODEL];

// =====================================================================
// helpers
// =====================================================================
__device__ __forceinline__ float rnaf(float x) {
    uint32_t u;
    asm("cvt.rna.tf32.f32 %0, %1;" : "=r"(u) : "f"(x));
    return __uint_as_float(u);
}

__device__ __forceinline__ void cpasync16(uint32_t saddr, const void* gaddr) {
    asm volatile("cp.async.cg.shared.global [%0], [%1], 16;" :: "r"(saddr), "l"(gaddr) : "memory");
}

__device__ __forceinline__ void mma_tf32(float c[4], const uint32_t a[4], const uint32_t b[2]) {
    asm volatile(
        "mma.sync.aligned.m16n8k8.row.col.f32.tf32.tf32.f32 "
        "{%0,%1,%2,%3}, {%4,%5,%6,%7}, {%8,%9}, {%0,%1,%2,%3};"
        : "+f"(c[0]), "+f"(c[1]), "+f"(c[2]), "+f"(c[3])
        : "r"(a[0]), "r"(a[1]), "r"(a[2]), "r"(a[3]), "r"(b[0]), "r"(b[1]));
}

__device__ __forceinline__ void ldsm_x4(uint32_t r[4], uint32_t addr) {
    asm volatile("ldmatrix.sync.aligned.m8n8.x4.shared.b16 {%0,%1,%2,%3}, [%4];"
                 : "=r"(r[0]), "=r"(r[1]), "=r"(r[2]), "=r"(r[3]) : "r"(addr));
}

// =====================================================================
// fused tf32-rounding + bias-fusion pass
// =====================================================================
#define N4_BIG (SEQ * DMODEL / 4)
#define N4_KV  (KVDIM * DMODEL / 4)
#define CVT_TOTAL (3 * N4_BIG + 2 * N4_KV)

__global__ void cvt_all_kernel(
    const float4* __restrict__ x,  const float4* __restrict__ wq,
    const float4* __restrict__ wk, const float4* __restrict__ wv,
    const float4* __restrict__ wo,
    const float*  __restrict__ bq, const float* __restrict__ bk,
    const float*  __restrict__ bv,
    float4* __restrict__ xt, float4* __restrict__ wqkv,
    float4* __restrict__ wot, float* __restrict__ bqkv)
{
    int i = blockIdx.x * blockDim.x + threadIdx.x;
    if (i < CVT_TOTAL) {
        const float4* src;
        float4* dst;
        int j = i;
        if (j < N4_BIG)                    { src = x;  dst = xt; }
        else if ((j -= N4_BIG) < N4_BIG)   { src = wq; dst = wqkv; }
        else if ((j -= N4_BIG) < N4_KV)    { src = wk; dst = wqkv + N4_BIG; }
        else if ((j -= N4_KV)  < N4_KV)    { src = wv; dst = wqkv + N4_BIG + N4_KV; }
        else { j -= N4_KV;                   src = wo; dst = wot; }
        float4 v = src[j];
        float4 o;
        o.x = rnaf(v.x); o.y = rnaf(v.y); o.z = rnaf(v.z); o.w = rnaf(v.w);
        dst[j] = o;
    } else {
        int j = i - CVT_TOTAL;
        if (j < NQKV) {
            float v;
            if (j < DMODEL)              v = bq[j];
            else if (j < DMODEL + KVDIM) v = bk[j - DMODEL];
            else                         v = bv[j - DMODEL - KVDIM];
            bqkv[j] = v;
        }
    }
}

// =====================================================================
// tf32 mma.sync GEMM (R10 proven config): CTA 128x128, 8 warps (2x4),
// warp tile 64x32, BK=32, 3-stage cp.async, 2 CTAs/SM.
// =====================================================================
#define BK      32
#define PAD     36
#define TILE_F  (128 * PAD)
#define STAGE_F (2 * TILE_F)
#define NSTAGE  3
#define GEMM_SMEM_BYTES (NSTAGE * STAGE_F * 4)

template <bool ROUND>
__global__ __launch_bounds__(256, 2) void gemm_tf32(
    const float* __restrict__ A, const float* __restrict__ B,
    const float* __restrict__ bias, float* __restrict__ C,
    int M, int N, int K)
{
    extern __shared__ float sm[];

    const int tid  = threadIdx.x;
    const int wid  = tid >> 5;
    const int lane = tid & 31;
    const int gid  = lane >> 2;
    const int tig  = lane & 3;
    const int wm   = wid >> 2;
    const int wn   = wid & 3;
    const int bm   = blockIdx.y * 128;
    const int bn   = blockIdx.x * 128;
    const int nchunk = K >> 5;

    const int arow = lane & 15;
    const int acsh = (lane >> 4) * 4;
    const int brow = ((lane >> 4) << 3) + (lane & 7);
    const int bcsh = ((lane >> 3) & 1) * 4;

    const uint32_t smem_u32 = (uint32_t)__cvta_generic_to_shared(sm);

    auto load_chunk = [&](int s, int j) {
        const uint32_t sA = smem_u32 + (s * STAGE_F) * 4;
        const uint32_t sB = sA + TILE_F * 4;
        const float* Ag = A + (size_t)bm * K + j * BK;
        const float* Bg = B + (size_t)bn * K + j * BK;
#pragma unroll
        for (int it = 0; it < 4; it++) {
            const int idx = tid + it * 256;
            const int r = idx >> 3;
            const int c = idx & 7;
            const uint32_t soff = (r * PAD + c * 4) * 4;
            cpasync16(sA + soff, Ag + (size_t)r * K + c * 4);
            cpasync16(sB + soff, Bg + (size_t)r * K + c * 4);
        }
        asm volatile("cp.async.commit_group;" ::: "memory");
    };

    float acc[4][4][4];
#pragma unroll
    for (int mf = 0; mf < 4; mf++)
#pragma unroll
        for (int nf = 0; nf < 4; nf++)
#pragma unroll
            for (int q = 0; q < 4; q++) acc[mf][nf][q] = 0.0f;

    load_chunk(0, 0);
    if (nchunk > 1) load_chunk(1, 1);

    int cs = 0;
    int ls = 2;
    for (int i = 0; i < nchunk; i++) {
        if (i + 1 < nchunk) {
            asm volatile("cp.async.wait_group 1;" ::: "memory");
        } else {
            asm volatile("cp.async.wait_group 0;" ::: "memory");
        }
        __syncthreads();

        const int j = i + 2;
        if (j < nchunk) {
            load_chunk(ls, j);
            ls = (ls == NSTAGE - 1) ? 0 : ls + 1;
        }

        const uint32_t stA = smem_u32 + (cs * STAGE_F) * 4;
        const uint32_t stB = stA + TILE_F * 4;
        const uint32_t aAddr = stA + ((wm * 64 + arow) * PAD + acsh) * 4;
        const uint32_t bAddr = stB + ((wn * 32 + brow) * PAD + bcsh) * 4;
        cs = (cs == NSTAGE - 1) ? 0 : cs + 1;

#pragma unroll
        for (int kk = 0; kk < 4; kk++) {
            const int k0 = kk * 8;
            uint32_t af[4][4];
#pragma unroll
            for (int mf = 0; mf < 4; mf++)
                ldsm_x4(af[mf], aAddr + (mf * 16 * PAD + k0) * 4);
            uint32_t bf[4][2];
#pragma unroll
            for (int np = 0; np < 2; np++) {
                uint32_t bt[4];
                ldsm_x4(bt, bAddr + (np * 16 * PAD + k0) * 4);
                bf[2 * np][0]     = bt[0]; bf[2 * np][1]     = bt[1];
                bf[2 * np + 1][0] = bt[2]; bf[2 * np + 1][1] = bt[3];
            }
#pragma unroll
            for (int mf = 0; mf < 4; mf++)
#pragma unroll
                for (int nf = 0; nf < 4; nf++)
                    mma_tf32(acc[mf][nf], af[mf], bf[nf]);
        }
    }

#pragma unroll
    for (int mf = 0; mf < 4; mf++) {
        const int row = bm + wm * 64 + mf * 16 + gid;
#pragma unroll
        for (int nf = 0; nf < 4; nf++) {
            const int col = bn + wn * 32 + nf * 8 + 2 * tig;
            const float b0 = bias[col], b1 = bias[col + 1];
            float2 v0, v1;
            if (ROUND) {
                v0.x = rnaf(acc[mf][nf][0] + b0); v0.y = rnaf(acc[mf][nf][1] + b1);
                v1.x = rnaf(acc[mf][nf][2] + b0); v1.y = rnaf(acc[mf][nf][3] + b1);
            } else {
                v0.x = acc[mf][nf][0] + b0; v0.y = acc[mf][nf][1] + b1;
                v1.x = acc[mf][nf][2] + b0; v1.y = acc[mf][nf][3] + b1;
            }
            *(float2*)&C[(size_t)row * N + col]       = v0;
            *(float2*)&C[(size_t)(row + 8) * N + col] = v1;
        }
    }
}

// =====================================================================
// QKV GEMM variant: CTA tile 128x192 (warp tile 64x48), BK=32,
// 2-stage cp.async, 2 CTAs/SM. Grid 16x16 = 256 CTAs = ONE wave.
// Output rna-rounded. Per-element accumulation identical to 128-wide.
// =====================================================================
#define TBN     192
#define AT192_F (128 * PAD)
#define BT192_F (TBN * PAD)
#define STG192_F (AT192_F + BT192_F)          // 11520 floats
#define G192_SMEM_BYTES (2 * STG192_F * 4)    // 92160 B

__global__ __launch_bounds__(256, 2) void gemm_tf32_n192(
    const float* __restrict__ A, const float* __restrict__ B,
    const float* __restrict__ bias, float* __restrict__ C,
    int M, int N, int K)
{
    extern __shared__ float sm[];

    const int tid  = threadIdx.x;
    const int wid  = tid >> 5;
    const int lane = tid & 31;
    const int gid  = lane >> 2;
    const int tig  = lane & 3;
    const int wm   = wid >> 2;        // 0..1 : 64-row slab
    const int wn   = wid & 3;         // 0..3 : 48-col slab
    const int bm   = blockIdx.y * 128;
    const int bn   = blockIdx.x * TBN;
    const int nchunk = K >> 5;

    const int arow = lane & 15;
    const int acsh = (lane >> 4) * 4;
    const int brow = ((lane >> 4) << 3) + (lane & 7);
    const int bcsh = ((lane >> 3) & 1) * 4;

    const uint32_t smem_u32 = (uint32_t)__cvta_generic_to_shared(sm);

    auto load_chunk = [&](int s, int j) {
        const uint32_t sA = smem_u32 + (s * STG192_F) * 4;
        const uint32_t sB = sA + AT192_F * 4;
        const float* Ag = A + (size_t)bm * K + j * BK;
        const float* Bg = B + (size_t)bn * K + j * BK;
#pragma unroll
        for (int it = 0; it < 4; it++) {
            const int idx = tid + it * 256;      // 0..1023 (A: 128 rows x 8 chunks)
            const int r = idx >> 3;
            const int c = idx & 7;
            cpasync16(sA + (r * PAD + c * 4) * 4, Ag + (size_t)r * K + c * 4);
        }
#pragma unroll
        for (int it = 0; it < 6; it++) {
            const int idx = tid + it * 256;      // 0..1535 (B: 192 rows x 8 chunks)
            const int r = idx >> 3;
            const int c = idx & 7;
            cpasync16(sB + (r * PAD + c * 4) * 4, Bg + (size_t)r * K + c * 4);
        }
        asm volatile("cp.async.commit_group;" ::: "memory");
    };

    float acc[4][6][4];
#pragma unroll
    for (int mf = 0; mf < 4; mf++)
#pragma unroll
        for (int nf = 0; nf < 6; nf++)
#pragma unroll
            for (int q = 0; q < 4; q++) acc[mf][nf][q] = 0.0f;

    load_chunk(0, 0);

    for (int i = 0; i < nchunk; i++) {
        if (i + 1 < nchunk) {
            load_chunk((i + 1) & 1, i + 1);
            asm volatile("cp.async.wait_group 1;" ::: "memory");
        } else {
            asm volatile("cp.async.wait_group 0;" ::: "memory");
        }
        __syncthreads();

        const uint32_t stA = smem_u32 + ((i & 1) * STG192_F) * 4;
        const uint32_t stB = stA + AT192_F * 4;
        const uint32_t aAddr = stA + ((wm * 64 + arow) * PAD + acsh) * 4;
        const uint32_t bAddr = stB + ((wn * 48 + brow) * PAD + bcsh) * 4;

#pragma unroll
        for (int kk = 0; kk < 4; kk++) {
            const int k0 = kk * 8;
            uint32_t af[4][4];
#pragma unroll
            for (int mf = 0; mf < 4; mf++)
                ldsm_x4(af[mf], aAddr + (mf * 16 * PAD + k0) * 4);
            uint32_t bf[6][2];
#pragma unroll
            for (int np = 0; np < 3; np++) {
                uint32_t bt[4];
                ldsm_x4(bt, bAddr + (np * 16 * PAD + k0) * 4);
                bf[2 * np][0]     = bt[0]; bf[2 * np][1]     = bt[1];
                bf[2 * np + 1][0] = bt[2]; bf[2 * np + 1][1] = bt[3];
            }
#pragma unroll
            for (int mf = 0; mf < 4; mf++)
#pragma unroll
                for (int nf = 0; nf < 6; nf++)
                    mma_tf32(acc[mf][nf], af[mf], bf[nf]);
        }
        __syncthreads();
    }

#pragma unroll
    for (int mf = 0; mf < 4; mf++) {
        const int row = bm + wm * 64 + mf * 16 + gid;
#pragma unroll
        for (int nf = 0; nf < 6; nf++) {
            const int col = bn + wn * 48 + nf * 8 + 2 * tig;
            const float b0 = bias[col], b1 = bias[col + 1];
            float2 v0, v1;
            v0.x = rnaf(acc[mf][nf][0] + b0); v0.y = rnaf(acc[mf][nf][1] + b1);
            v1.x = rnaf(acc[mf][nf][2] + b0); v1.y = rnaf(acc[mf][nf][3] + b1);
            *(float2*)&C[(size_t)row * N + col]       = v0;
            *(float2*)&C[(size_t)(row + 8) * N + col] = v1;
        }
    }
}

// =====================================================================
// Flash attention v4: paired q-blocks for causal load balance.
// =====================================================================
#define QT    128
#define KT    64
#define DPAD  132
#define VPAD  68
#define PPAD  68
#define KOFF  0
#define VOFF  (2 * KT * DPAD)
#define POFF  (VOFF + 2 * QT * VPAD)
#define ATTN_F (POFF + QT * PPAD)
#define ATTN_SMEM_BYTES (ATTN_F * 4)
#define NQB   (SEQ / QT)                 // 16

__global__ __launch_bounds__(256, 1) void attn_tc_kernel(
    const float* __restrict__ QKV, float* __restrict__ Y)
{
    extern __shared__ float sm[];

    const int h    = blockIdx.y;
    const int pair = blockIdx.x;            // 0..7
    const int kvh  = h >> 2;
    const int tid  = threadIdx.x;
    const int wid  = tid >> 5;
    const int lane = tid & 31;
    const int gid  = lane >> 2;
    const int tig  = lane & 3;
    const int w16  = wid * 16;

    const int arow = lane & 15;
    const int acsh = (lane >> 4) * 4;
    const int brow = ((lane >> 4) << 3) + (lane & 7);
    const int bcsh = ((lane >> 3) & 1) * 4;

    const uint32_t smem_u32 = (uint32_t)__cvta_generic_to_shared(sm);

    const float* Qg = QKV + h * DK;
    const float* Kg = QKV + DMODEL + kvh * DK;
    const float* Vg = QKV + DMODEL + KVDIM + kvh * DK;

    const uint32_t kBase = smem_u32 + (KOFF + brow * DPAD + bcsh) * 4;
    const uint32_t vBase = smem_u32 + (VOFF + brow * VPAD + bcsh) * 4;
    const uint32_t pAddr = smem_u32 + (POFF + (w16 + arow) * PPAD + acsh) * 4;
    float* Ps = sm + POFF;

    const int vbr0 = tid >> 5;
    const int vbc0 = tid & 31;
    const float scale = 0.08838834764831845f;

    auto issue_K = [&](int jbi, int buf) {
        const float* src = Kg + (size_t)(jbi * KT) * NQKV;
        const uint32_t dst = smem_u32 + (KOFF + buf * KT * DPAD) * 4;
#pragma unroll
        for (int it = 0; it < 8; it++) {
            const int idx = tid + it * 256;
            const int r = idx >> 5;
            const int c = idx & 31;
            cpasync16(dst + (r * DPAD + c * 4) * 4, src + (size_t)r * NQKV + c * 4);
        }
        asm volatile("cp.async.commit_group;" ::: "memory");
    };
    auto ldg_V = [&](int jbi, float4 vb[2][4]) {
        const float* src = Vg + (size_t)(jbi * KT) * NQKV;
#pragma unroll
        for (int b = 0; b < 2; b++) {
            const int br = vbr0 + b * 8;
#pragma unroll
            for (int j = 0; j < 4; j++)
                vb[b][j] = *(const float4*)&src[(size_t)(br * 4 + j) * NQKV + vbc0 * 4];
        }
    };
    auto sts_Vt = [&](int buf, float4 vb[2][4]) {
        float* Vt = sm + VOFF + buf * QT * VPAD;
#pragma unroll
        for (int b = 0; b < 2; b++) {
            const int br = vbr0 + b * 8;
            const float* v = (const float*)vb[b];
#pragma unroll
            for (int k = 0; k < 4; k++) {
                float4 w;
                w.x = v[0 * 4 + k]; w.y = v[1 * 4 + k];
                w.z = v[2 * 4 + k]; w.w = v[3 * 4 + k];
                *(float4*)&Vt[(vbc0 * 4 + k) * VPAD + br * 4] = w;
            }
        }
    };

    for (int half = 0; half < 2; half++) {
        const int qb = half ? pair : (NQB - 1 - pair);
        const int q0 = qb * QT;
        const int rg0 = q0 + w16 + gid;
        const int rg1 = rg0 + 8;
        const int njb = 2 * qb + 2;

        asm volatile("cp.async.wait_group 0;" ::: "memory");
        __syncthreads();

        // ---- stage Q (pre-rounded tf32) into K region, ldsm to regs ----
        for (int i = tid; i < QT * 32; i += 256) {
            const int r  = i >> 5;
            const int c4 = (i & 31) << 2;
            *(float4*)&sm[r * DPAD + c4] = *(const float4*)&Qg[(size_t)(q0 + r) * NQKV + c4];
        }
        __syncthreads();
        uint32_t qf[16][4];
        {
            const uint32_t qAddr = smem_u32 + ((w16 + arow) * DPAD + acsh) * 4;
#pragma unroll
            for (int kk = 0; kk < 16; kk++)
                ldsm_x4(qf[kk], qAddr + kk * 32);
        }
        __syncthreads();

        float o_acc[16][4];
#pragma unroll
        for (int nf = 0; nf < 16; nf++)
#pragma unroll
            for (int q = 0; q < 4; q++) o_acc[nf][q] = 0.0f;
        float m0 = -1e30f, m1 = -1e30f, l0 = 0.0f, l1 = 0.0f;

        issue_K(0, 0);
        {
            float4 vb[2][4];
            ldg_V(0, vb);
            sts_Vt(0, vb);
        }

        for (int jb = 0; jb < njb; jb++) {
            const int buf = jb & 1;

            asm volatile("cp.async.wait_group 0;" ::: "memory");
            __syncthreads();

            const bool have_next = (jb + 1 < njb);
            float4 vb[2][4];
            if (have_next) {
                issue_K(jb + 1, buf ^ 1);
                ldg_V(jb + 1, vb);
            }

            // ---- S = Q @ K^T ----
            float s[8][4];
#pragma unroll
            for (int nf = 0; nf < 8; nf++)
#pragma unroll
                for (int q = 0; q < 4; q++) s[nf][q] = 0.0f;

            const uint32_t kAddr = kBase + (buf * KT * DPAD) * 4;
#pragma unroll
            for (int kk = 0; kk < 16; kk++) {
                const int kd = kk * 8;
                uint32_t bf[8][2];
#pragma unroll
                for (int np = 0; np < 4; np++) {
                    uint32_t bt[4];
                    ldsm_x4(bt, kAddr + (np * 16 * DPAD + kd) * 4);
                    bf[2 * np][0]     = bt[0]; bf[2 * np][1]     = bt[1];
                    bf[2 * np + 1][0] = bt[2]; bf[2 * np + 1][1] = bt[3];
                }
#pragma unroll
                for (int nf = 0; nf < 8; nf++)
                    mma_tf32(s[nf], qf[kk], bf[nf]);
            }

            // ---- scale + mask + online softmax ----
            const int k0 = jb * KT;
            const bool need_mask = (jb >= 2 * qb);
            float mx0 = -1e30f, mx1 = -1e30f;
#pragma unroll
            for (int nf = 0; nf < 8; nf++) {
#pragma unroll
                for (int e = 0; e < 2; e++) {
                    const int jg = k0 + nf * 8 + 2 * tig + e;
                    float v0 = s[nf][e]     * scale;
                    float v1 = s[nf][2 + e] * scale;
                    if (need_mask) {
                        if (jg > rg0) v0 = -1e30f;
                        if (jg > rg1) v1 = -1e30f;
                    }
                    s[nf][e]     = v0;
                    s[nf][2 + e] = v1;
                    mx0 = fmaxf(mx0, v0);
                    mx1 = fmaxf(mx1, v1);
                }
            }
            mx0 = fmaxf(mx0, __shfl_xor_sync(0xffffffffu, mx0, 1));
            mx0 = fmaxf(mx0, __shfl_xor_sync(0xffffffffu, mx0, 2));
            mx1 = fmaxf(mx1, __shfl_xor_sync(0xffffffffu, mx1, 1));
            mx1 = fmaxf(mx1, __shfl_xor_sync(0xffffffffu, mx1, 2));

            const float mn0 = fmaxf(m0, mx0);
            const float mn1 = fmaxf(m1, mx1);
            const float al0 = __expf(m0 - mn0);
            const float al1 = __expf(m1 - mn1);
            m0 = mn0; m1 = mn1;

            float sum0 = 0.0f, sum1 = 0.0f;
#pragma unroll
            for (int nf = 0; nf < 8; nf++) {
                float p00 = __expf(s[nf][0] - mn0);
                float p01 = __expf(s[nf][1] - mn0);
                float p10 = __expf(s[nf][2] - mn1);
                float p11 = __expf(s[nf][3] - mn1);
                sum0 += p00 + p01;
                sum1 += p10 + p11;
                float2 w0; w0.x = rnaf(p00); w0.y = rnaf(p01);
                float2 w1; w1.x = rnaf(p10); w1.y = rnaf(p11);
                const int pc = nf * 8 + 2 * tig;
                *(float2*)&Ps[(w16 + gid)     * PPAD + pc] = w0;
                *(float2*)&Ps[(w16 + gid + 8) * PPAD + pc] = w1;
            }
            sum0 += __shfl_xor_sync(0xffffffffu, sum0, 1);
            sum0 += __shfl_xor_sync(0xffffffffu, sum0, 2);
            sum1 += __shfl_xor_sync(0xffffffffu, sum1, 1);
            sum1 += __shfl_xor_sync(0xffffffffu, sum1, 2);
            l0 = l0 * al0 + sum0;
            l1 = l1 * al1 + sum1;

#pragma unroll
            for (int nf = 0; nf < 16; nf++) {
                o_acc[nf][0] *= al0; o_acc[nf][1] *= al0;
                o_acc[nf][2] *= al1; o_acc[nf][3] *= al1;
            }

            if (have_next) sts_Vt(buf ^ 1, vb);
            __syncwarp();

            // ---- O += P @ V ----
            const uint32_t vAddr = vBase + (buf * QT * VPAD) * 4;
#pragma unroll
            for (int kk = 0; kk < 8; kk++) {
                const int kb = kk * 8;
                uint32_t a[4];
                ldsm_x4(a, pAddr + kb * 4);
                uint32_t bf[16][2];
#pragma unroll
                for (int np = 0; np < 8; np++) {
                    uint32_t bt[4];
                    ldsm_x4(bt, vAddr + (np * 16 * VPAD + kb) * 4);
                    bf[2 * np][0]     = bt[0]; bf[2 * np][1]     = bt[1];
                    bf[2 * np + 1][0] = bt[2]; bf[2 * np + 1][1] = bt[3];
                }
#pragma unroll
                for (int nf = 0; nf < 16; nf++)
                    mma_tf32(o_acc[nf], a, bf[nf]);
            }
        }

        // ---- epilogue for this half ----
        const float inv0 = 1.0f / l0;
        const float inv1 = 1.0f / l1;
#pragma unroll
        for (int nf = 0; nf < 16; nf++) {
            const int col = h * DK + nf * 8 + 2 * tig;
            float2 v0, v1;
            v0.x = rnaf(o_acc[nf][0] * inv0); v0.y = rnaf(o_acc[nf][1] * inv0);
            v1.x = rnaf(o_acc[nf][2] * inv1); v1.y = rnaf(o_acc[nf][3] * inv1);
            *(float2*)&Y[(size_t)rg0 * DMODEL + col] = v0;
            *(float2*)&Y[(size_t)rg1 * DMODEL + col] = v1;
        }
    }
}

// =====================================================================
// launch
// =====================================================================
extern "C" void kernel_launch(void* const* d_in, const int* in_sizes, int n_in,
                              void* d_out, int out_size)
{
    const float* x  = (const float*)d_in[0];
    const float* Wq = (const float*)d_in[1];
    const float* bq = (const float*)d_in[2];
    const float* Wk = (const float*)d_in[3];
    const float* bk = (const float*)d_in[4];
    const float* Wv = (const float*)d_in[5];
    const float* bv = (const float*)d_in[6];
    const float* Wo = (const float*)d_in[7];
    const float* bo = (const float*)d_in[8];
    float* out = (float*)d_out;

    float *QKVb, *Yb, *xt, *Wqkv, *bqkv, *Wot;
    cudaGetSymbolAddress((void**)&QKVb, g_QKV);
    cudaGetSymbolAddress((void**)&Yb,   g_Y);
    cudaGetSymbolAddress((void**)&xt,   g_xt);
    cudaGetSymbolAddress((void**)&Wqkv, g_Wqkv);
    cudaGetSymbolAddress((void**)&bqkv, g_bqkv);
    cudaGetSymbolAddress((void**)&Wot,  g_Wot);

    cudaFuncSetAttribute(gemm_tf32<false>,
                         cudaFuncAttributeMaxDynamicSharedMemorySize, GEMM_SMEM_BYTES);
    cudaFuncSetAttribute(gemm_tf32_n192,
                         cudaFuncAttributeMaxDynamicSharedMemorySize, G192_SMEM_BYTES);
    cudaFuncSetAttribute(attn_tc_kernel,
                         cudaFuncAttributeMaxDynamicSharedMemorySize, ATTN_SMEM_BYTES);

    dim3 blk(256);

    const int cvt_n = CVT_TOTAL + NQKV;
    cvt_all_kernel<<<(cvt_n + 255) / 256, 256>>>(
        (const float4*)x, (const float4*)Wq, (const float4*)Wk,
        (const float4*)Wv, (const float4*)Wo,
        bq, bk, bv,
        (float4*)xt, (float4*)Wqkv, (float4*)Wot, bqkv);

    // fused QKV projection: 128x192 tiles, 256 CTAs = one wave
    gemm_tf32_n192<<<dim3(NQKV / TBN, SEQ / 128), blk, G192_SMEM_BYTES>>>(
        xt, Wqkv, bqkv, QKVb, SEQ, NQKV, DMODEL);

    attn_tc_kernel<<<dim3(NQB / 2, NHEADS), blk, ATTN_SMEM_BYTES>>>(QKVb, Yb);

    gemm_tf32<false><<<dim3(DMODEL / 128, SEQ / 128), blk, GEMM_SMEM_BYTES>>>(
        Yb, Wot, bo, out, SEQ, DMODEL, DMODEL);
}